// round 1
// baseline (speedup 1.0000x reference)
#include <cuda_runtime.h>

#define TB      256     // threads per block == samples per block
#define NN      64      // input dim
#define HH      256     // hidden dim
#define OO      64      // output dim
#define MAXIT   30
#define TOLV    1e-7f

#define SXS     65      // x tile row stride (pad for bank conflicts)
#define SW2S    68      // W2^T row stride (4-way-conflict write, 16B aligned rows)

// smem layout (floats):
//   sx   : TB*SXS          = 16640
//   sw1  : HH*NN           = 16384
//   sw2  : HH*SW2S         = 17408   (transposed: [j][k])
//   sc2  : NN (=-2r)
//   srr  : NN (r)
//   sb1  : HH
//   sb2  : OO
#define SMEM_FLOATS (TB*SXS + HH*NN + HH*SW2S + NN + NN + HH + OO)

__global__ __launch_bounds__(TB, 1)
void aniso_kernel(const float* __restrict__ x,  const float* __restrict__ r,
                  const float* __restrict__ W1, const float* __restrict__ b1,
                  const float* __restrict__ W2, const float* __restrict__ b2,
                  float* __restrict__ out)
{
    extern __shared__ float sm[];
    float* sx  = sm;
    float* sw1 = sx  + TB * SXS;
    float* sw2 = sw1 + HH * NN;
    float* sc2 = sw2 + HH * SW2S;
    float* srr = sc2 + NN;
    float* sb1 = srr + NN;
    float* sb2 = sb1 + HH;

    const int tid = threadIdx.x;
    const long long b0 = (long long)blockIdx.x * TB;

    // ---- stage weights / constants ----
    for (int idx = tid; idx < HH * NN; idx += TB) sw1[idx] = W1[idx];
    for (int idx = tid; idx < OO * HH; idx += TB) {
        int k = idx >> 8;        // output index (row of W2)
        int j = idx & 255;       // hidden index
        sw2[j * SW2S + k] = W2[idx];
    }
    if (tid < NN) { float rv = r[tid]; srr[tid] = rv; sc2[tid] = -2.0f * rv; }
    for (int idx = tid; idx < HH; idx += TB) sb1[idx] = b1[idx];
    if (tid < OO) sb2[tid] = b2[tid];

    // ---- stage x tile (coalesced) ----
    const float* xg = x + b0 * NN;
    for (int idx = tid; idx < TB * NN; idx += TB) {
        int rr = idx >> 6, cc = idx & 63;
        sx[rr * SXS + cc] = xg[idx];
    }
    __syncthreads();

    // ---- per-thread Newton solve of sum_i exp(-2 r_i s) x_i^2 = 1 ----
    float xsq[NN];
    #pragma unroll
    for (int i = 0; i < NN; i++) {
        float v = sx[tid * SXS + i];
        xsq[i] = v * v;
    }

    float s = 0.0f;
    #pragma unroll 1
    for (int it = 0; it < MAXIT; it++) {
        float v0 = -1.0f, v1 = 0.0f;      // F(s) split accumulators
        float d0 = 0.0f,  d1 = 0.0f;      // F'(s) split accumulators
        #pragma unroll
        for (int i = 0; i < NN; i += 2) {
            float c0 = sc2[i],     c1 = sc2[i + 1];
            float e0 = __expf(c0 * s), e1 = __expf(c1 * s);
            float p0 = e0 * xsq[i],    p1 = e1 * xsq[i + 1];
            v0 += p0;                 v1 += p1;
            d0 = fmaf(c0, p0, d0);    d1 = fmaf(c1, p1, d1);
        }
        float val  = v0 + v1;
        float dval = d0 + d1;
        if (fabsf(val) < TOLV || dval == 0.0f) break;   // converged / all-zero row
        s -= val / dval;
    }

    // ---- x_sphere and output scale ----
    float xv[NN];
    #pragma unroll
    for (int i = 0; i < NN; i++)
        xv[i] = sx[tid * SXS + i] * __expf(-srr[i] * s);
    const float escale = __expf(s);     // NU = 1

    // ---- fused MLP: out = relu(xv @ W1^T + b1) @ W2^T + b2 ----
    float acc[OO];
    #pragma unroll
    for (int k = 0; k < OO; k++) acc[k] = sb2[k];

    #pragma unroll 1
    for (int j = 0; j < HH; j += 4) {
        float h0 = sb1[j + 0], h1 = sb1[j + 1], h2 = sb1[j + 2], h3 = sb1[j + 3];
        const float4* w0 = (const float4*)(sw1 + (j + 0) * NN);
        const float4* w1r = (const float4*)(sw1 + (j + 1) * NN);
        const float4* w2r = (const float4*)(sw1 + (j + 2) * NN);
        const float4* w3r = (const float4*)(sw1 + (j + 3) * NN);
        #pragma unroll
        for (int i4 = 0; i4 < NN / 4; i4++) {
            float4 a0 = w0[i4], a1 = w1r[i4], a2 = w2r[i4], a3 = w3r[i4];
            float q0 = xv[4*i4+0], q1 = xv[4*i4+1], q2 = xv[4*i4+2], q3 = xv[4*i4+3];
            h0 = fmaf(q0, a0.x, h0); h0 = fmaf(q1, a0.y, h0);
            h0 = fmaf(q2, a0.z, h0); h0 = fmaf(q3, a0.w, h0);
            h1 = fmaf(q0, a1.x, h1); h1 = fmaf(q1, a1.y, h1);
            h1 = fmaf(q2, a1.z, h1); h1 = fmaf(q3, a1.w, h1);
            h2 = fmaf(q0, a2.x, h2); h2 = fmaf(q1, a2.y, h2);
            h2 = fmaf(q2, a2.z, h2); h2 = fmaf(q3, a2.w, h2);
            h3 = fmaf(q0, a3.x, h3); h3 = fmaf(q1, a3.y, h3);
            h3 = fmaf(q2, a3.z, h3); h3 = fmaf(q3, a3.w, h3);
        }
        h0 = fmaxf(h0, 0.0f); h1 = fmaxf(h1, 0.0f);
        h2 = fmaxf(h2, 0.0f); h3 = fmaxf(h3, 0.0f);

        const float4* v0p = (const float4*)(sw2 + (j + 0) * SW2S);
        const float4* v1p = (const float4*)(sw2 + (j + 1) * SW2S);
        const float4* v2p = (const float4*)(sw2 + (j + 2) * SW2S);
        const float4* v3p = (const float4*)(sw2 + (j + 3) * SW2S);
        #pragma unroll
        for (int k4 = 0; k4 < OO / 4; k4++) {
            float4 c0 = v0p[k4], c1 = v1p[k4], c2 = v2p[k4], c3 = v3p[k4];
            int k = 4 * k4;
            acc[k+0] = fmaf(h0, c0.x, acc[k+0]);
            acc[k+1] = fmaf(h0, c0.y, acc[k+1]);
            acc[k+2] = fmaf(h0, c0.z, acc[k+2]);
            acc[k+3] = fmaf(h0, c0.w, acc[k+3]);
            acc[k+0] = fmaf(h1, c1.x, acc[k+0]);
            acc[k+1] = fmaf(h1, c1.y, acc[k+1]);
            acc[k+2] = fmaf(h1, c1.z, acc[k+2]);
            acc[k+3] = fmaf(h1, c1.w, acc[k+3]);
            acc[k+0] = fmaf(h2, c2.x, acc[k+0]);
            acc[k+1] = fmaf(h2, c2.y, acc[k+1]);
            acc[k+2] = fmaf(h2, c2.z, acc[k+2]);
            acc[k+3] = fmaf(h2, c2.w, acc[k+3]);
            acc[k+0] = fmaf(h3, c3.x, acc[k+0]);
            acc[k+1] = fmaf(h3, c3.y, acc[k+1]);
            acc[k+2] = fmaf(h3, c3.z, acc[k+2]);
            acc[k+3] = fmaf(h3, c3.w, acc[k+3]);
        }
    }

    // ---- stage outputs to smem (reuse sx), then coalesced store ----
    __syncthreads();   // everyone done reading sx
    #pragma unroll
    for (int k = 0; k < OO; k++)
        sx[tid * SXS + k] = acc[k] * escale;
    __syncthreads();

    float* og = out + b0 * OO;
    for (int idx = tid; idx < TB * OO; idx += TB) {
        int rr = idx >> 6, cc = idx & 63;
        og[idx] = sx[rr * SXS + cc];
    }
}

extern "C" void kernel_launch(void* const* d_in, const int* in_sizes, int n_in,
                              void* d_out, int out_size)
{
    const float* x  = (const float*)d_in[0];
    const float* r  = (const float*)d_in[1];
    const float* W1 = (const float*)d_in[2];
    const float* b1 = (const float*)d_in[3];
    const float* W2 = (const float*)d_in[4];
    const float* b2 = (const float*)d_in[5];
    float* out = (float*)d_out;

    const int B = in_sizes[0] / NN;          // 262144
    const size_t smem = SMEM_FLOATS * sizeof(float);   // ~203.5 KB

    cudaFuncSetAttribute(aniso_kernel,
                         cudaFuncAttributeMaxDynamicSharedMemorySize, (int)smem);
    aniso_kernel<<<B / TB, TB, smem>>>(x, r, W1, b1, W2, b2, out);
}